// round 16
// baseline (speedup 1.0000x reference)
#include <cuda_runtime.h>
#include <math.h>

#define Hc 64
#define Dc 64
#define Vc 128
#define Gc 32
#define NWARPS 8
#define NSTREAM (NWARPS * 2)
#define CHUNKS 8
#define BMAX 2048

// ---- scratch (device globals; no allocation in kernel_launch) ----
__device__ float g_qp [BMAX * Dc];                 // q_proj, pre-scaled
__device__ float g_mx [BMAX * CHUNKS];
__device__ float g_den[BMAX * CHUNKS];
__device__ float g_acc[BMAX * CHUNKS * Dc];

// ================= k0: q_proj = (query @ Wq + bq) / sqrt(D) =================
__global__ __launch_bounds__(64)
void qproj_kernel(const float* __restrict__ query,
                  const float* __restrict__ Wq,
                  const float* __restrict__ bq)
{
    __shared__ float qsh[Hc];
    const int b = blockIdx.x, d = threadIdx.x;
    qsh[d] = query[(size_t)b * Hc + d];
    __syncthreads();
    float s = bq[d];
    #pragma unroll
    for (int h = 0; h < Hc; ++h) s += qsh[h] * Wq[h * Dc + d];
    g_qp[b * Dc + d] = s * 0.125f;
}

// ============ k1: streaming online-softmax over one 256-row chunk ===========
__global__ __launch_bounds__(256, 6)
void chunk_kernel(const float* __restrict__ memory, int M)
{
    __shared__ float wmx[NSTREAM], wden[NSTREAM];
    __shared__ float wacc[NSTREAM][Dc];

    const int bid   = blockIdx.x;
    const int b     = bid / CHUNKS;
    const int chunk = bid % CHUNKS;
    const int tid   = threadIdx.x;
    const int w     = tid >> 5;
    const int lane  = tid & 31;
    const int half  = lane >> 4;
    const int laneq = lane & 15;

    const float4 qp4 = ((const float4*)(g_qp + b * Dc))[laneq];
    const float4* __restrict__ mem4 =
        (const float4*)(memory + (size_t)b * (size_t)M * Dc);

    const int rows_per_chunk = M / CHUNKS;          // 256
    const int row0 = chunk * rows_per_chunk;
    const int rows_per_iter = NWARPS * 2 * 4;       // 64

    float  mx  = -INFINITY;
    float  den = 0.f;
    float4 acc = { 0.f, 0.f, 0.f, 0.f };

    for (int it = row0; it < row0 + rows_per_chunk; it += rows_per_iter) {
        const int rbase = it + w * 8 + half;

        float4 v0 = mem4[(size_t)(rbase + 0) * 16 + laneq];
        float4 v1 = mem4[(size_t)(rbase + 2) * 16 + laneq];
        float4 v2 = mem4[(size_t)(rbase + 4) * 16 + laneq];
        float4 v3 = mem4[(size_t)(rbase + 6) * 16 + laneq];

        float s0 = qp4.x*v0.x + qp4.y*v0.y + qp4.z*v0.z + qp4.w*v0.w;
        float s1 = qp4.x*v1.x + qp4.y*v1.y + qp4.z*v1.z + qp4.w*v1.w;
        float s2 = qp4.x*v2.x + qp4.y*v2.y + qp4.z*v2.z + qp4.w*v2.w;
        float s3 = qp4.x*v3.x + qp4.y*v3.y + qp4.z*v3.z + qp4.w*v3.w;

        #pragma unroll
        for (int o = 1; o < 16; o <<= 1) {
            s0 += __shfl_xor_sync(0xffffffffu, s0, o);
            s1 += __shfl_xor_sync(0xffffffffu, s1, o);
            s2 += __shfl_xor_sync(0xffffffffu, s2, o);
            s3 += __shfl_xor_sync(0xffffffffu, s3, o);
        }

        float m4 = fmaxf(fmaxf(s0, s1), fmaxf(s2, s3));
        float mn = fmaxf(mx, m4);
        float corr = __expf(mx - mn);     // exp(-inf)=0 on first iteration
        float e0 = __expf(s0 - mn);
        float e1 = __expf(s1 - mn);
        float e2 = __expf(s2 - mn);
        float e3 = __expf(s3 - mn);

        den   = den * corr + ((e0 + e1) + (e2 + e3));
        acc.x = acc.x * corr + (e0*v0.x + e1*v1.x + e2*v2.x + e3*v3.x);
        acc.y = acc.y * corr + (e0*v0.y + e1*v1.y + e2*v2.y + e3*v3.y);
        acc.z = acc.z * corr + (e0*v0.z + e1*v1.z + e2*v2.z + e3*v3.z);
        acc.w = acc.w * corr + (e0*v0.w + e1*v1.w + e2*v2.w + e3*v3.w);
        mx = mn;
    }

    // ---- merge 16 streams -> one partial per CTA, write to scratch ----
    const int sid = w * 2 + half;
    if (laneq == 0) { wmx[sid] = mx; wden[sid] = den; }
    *(float4*)(&wacc[sid][4 * laneq]) = acc;
    __syncthreads();

    if (tid < Dc) {
        float gmx = wmx[0];
        #pragma unroll
        for (int i = 1; i < NSTREAM; ++i) gmx = fmaxf(gmx, wmx[i]);
        float gden = 0.f, r = 0.f;
        #pragma unroll
        for (int i = 0; i < NSTREAM; ++i) {
            float sc = __expf(wmx[i] - gmx);
            gden += sc * wden[i];
            r    += sc * wacc[i][tid];
        }
        g_acc[(size_t)bid * Dc + tid] = r;
        if (tid == 0) { g_mx[bid] = gmx; g_den[bid] = gden; }
    }
}

// =============== k2: merge chunks + gate MLP + Wo + Wc epilogue =============
__global__ __launch_bounds__(128)
void merge_kernel(const float* __restrict__ query,
                  const float* __restrict__ Wo,  const float* __restrict__ bo,
                  const float* __restrict__ Wg1, const float* __restrict__ bg1,
                  const float* __restrict__ Wg2, const float* __restrict__ bg2,
                  const float* __restrict__ null_vec,
                  const float* __restrict__ Wc,  const float* __restrict__ bc,
                  float* __restrict__ out_logits,
                  float* __restrict__ out_gate)
{
    __shared__ float qsh[Hc];
    __shared__ float cmx[CHUNKS], cden[CHUNKS];
    __shared__ float ret[Dc];
    __shared__ float osh[Hc];
    __shared__ float max_sim_sh;
    __shared__ float gate_sh;

    const int b    = blockIdx.x;
    const int tid  = threadIdx.x;
    const int lane = tid & 31;

    if (tid < Hc) qsh[tid] = query[(size_t)b * Hc + tid];
    if (tid < CHUNKS) {
        cmx[tid]  = g_mx [b * CHUNKS + tid];
        cden[tid] = g_den[b * CHUNKS + tid];
    }
    __syncthreads();

    if (tid < Dc) {
        float gmx = cmx[0];
        #pragma unroll
        for (int c = 1; c < CHUNKS; ++c) gmx = fmaxf(gmx, cmx[c]);
        float gden = 0.f, r = 0.f;
        #pragma unroll
        for (int c = 0; c < CHUNKS; ++c) {
            float sc = __expf(cmx[c] - gmx);
            gden += sc * cden[c];
            r    += sc * g_acc[(size_t)(b * CHUNKS + c) * Dc + tid];
        }
        ret[tid] = r / gden;
        if (tid == 0) max_sim_sh = gmx;
    }
    __syncthreads();

    // gate MLP (warp 0)
    if (tid < 32) {
        float hval = bg1[lane];
        #pragma unroll
        for (int h = 0; h < Hc; ++h) hval += qsh[h] * Wg1[h * Gc + lane];
        hval += max_sim_sh * Wg1[Hc * Gc + lane];
        hval = fmaxf(hval, 0.f);
        float z = hval * Wg2[lane];
        #pragma unroll
        for (int o = 16; o > 0; o >>= 1) z += __shfl_xor_sync(0xffffffffu, z, o);
        if (lane == 0) {
            z += bg2[0];
            gate_sh = 1.f / (1.f + __expf(-z));
        }
    }
    __syncthreads();

    const float gate = gate_sh;

    if (tid < Hc) {
        float rh = bo[tid];
        #pragma unroll
        for (int d = 0; d < Dc; ++d) rh += ret[d] * Wo[d * Hc + tid];
        osh[tid] = gate * rh + (1.f - gate) * null_vec[tid];
    }
    __syncthreads();

    if (tid < Vc) {
        float lg = bc[tid];
        #pragma unroll
        for (int h = 0; h < Hc; ++h) lg += osh[h] * Wc[h * Vc + tid];
        out_logits[(size_t)b * Vc + tid] = lg;
    }
    if (tid == 0) out_gate[b] = gate;
}

extern "C" void kernel_launch(void* const* d_in, const int* in_sizes, int n_in,
                              void* d_out, int out_size)
{
    const float* query    = (const float*)d_in[0];
    const float* memory   = (const float*)d_in[1];
    const float* Wq       = (const float*)d_in[2];
    const float* bq       = (const float*)d_in[3];
    const float* Wo       = (const float*)d_in[4];
    const float* bo       = (const float*)d_in[5];
    const float* Wg1      = (const float*)d_in[6];
    const float* bg1      = (const float*)d_in[7];
    const float* Wg2      = (const float*)d_in[8];
    const float* bg2      = (const float*)d_in[9];
    const float* null_vec = (const float*)d_in[10];
    const float* Wc       = (const float*)d_in[11];
    const float* bc       = (const float*)d_in[12];

    const int B = in_sizes[0] / Hc;
    const int M = in_sizes[1] / (B * Dc);

    float* out_logits = (float*)d_out;
    float* out_gate   = (float*)d_out + (size_t)B * Vc;

    qproj_kernel<<<B, 64>>>(query, Wq, bq);
    chunk_kernel<<<B * CHUNKS, 256>>>(memory, M);
    merge_kernel<<<B, 128>>>(query, Wo, bo, Wg1, bg1, Wg2, bg2,
                             null_vec, Wc, bc, out_logits, out_gate);
}

// round 17
// speedup vs baseline: 1.0017x; 1.0017x over previous
#include <cuda_runtime.h>
#include <math.h>

#define Hc 64
#define Dc 64
#define Vc 128
#define Gc 32
#define NWARPS 8
#define NSTREAM (NWARPS * 2)
#define CHUNKS 8
#define BMAX 2048

// ---- scratch (device globals; no allocation in kernel_launch) ----
__device__ float g_qp [BMAX * Dc];                 // q_proj, pre-scaled
__device__ float g_mx [BMAX * CHUNKS];
__device__ float g_den[BMAX * CHUNKS];
__device__ float g_acc[BMAX * CHUNKS * Dc];

// ================= k0: q_proj = (query @ Wq + bq) / sqrt(D) =================
__global__ __launch_bounds__(64)
void qproj_kernel(const float* __restrict__ query,
                  const float* __restrict__ Wq,
                  const float* __restrict__ bq)
{
    __shared__ float qsh[Hc];
    const int b = blockIdx.x, d = threadIdx.x;
    qsh[d] = query[(size_t)b * Hc + d];
    __syncthreads();
    float s = bq[d];
    #pragma unroll
    for (int h = 0; h < Hc; ++h) s += qsh[h] * Wq[h * Dc + d];
    g_qp[b * Dc + d] = s * 0.125f;
}

// ============ k1: streaming online-softmax over one 256-row chunk ===========
__global__ __launch_bounds__(256, 6)
void chunk_kernel(const float* __restrict__ memory, int M)
{
    __shared__ float wmx[NSTREAM], wden[NSTREAM];
    __shared__ float wacc[NSTREAM][Dc];

    const int bid   = blockIdx.x;
    const int b     = bid / CHUNKS;
    const int chunk = bid % CHUNKS;
    const int tid   = threadIdx.x;
    const int w     = tid >> 5;
    const int lane  = tid & 31;
    const int half  = lane >> 4;
    const int laneq = lane & 15;

    const float4 qp4 = ((const float4*)(g_qp + b * Dc))[laneq];
    const float4* __restrict__ mem4 =
        (const float4*)(memory + (size_t)b * (size_t)M * Dc);

    const int rows_per_chunk = M / CHUNKS;          // 256
    const int row0 = chunk * rows_per_chunk;
    const int rows_per_iter = NWARPS * 2 * 4;       // 64

    float  mx  = -INFINITY;
    float  den = 0.f;
    float4 acc = { 0.f, 0.f, 0.f, 0.f };

    for (int it = row0; it < row0 + rows_per_chunk; it += rows_per_iter) {
        const int rbase = it + w * 8 + half;

        float4 v0 = mem4[(size_t)(rbase + 0) * 16 + laneq];
        float4 v1 = mem4[(size_t)(rbase + 2) * 16 + laneq];
        float4 v2 = mem4[(size_t)(rbase + 4) * 16 + laneq];
        float4 v3 = mem4[(size_t)(rbase + 6) * 16 + laneq];

        float s0 = qp4.x*v0.x + qp4.y*v0.y + qp4.z*v0.z + qp4.w*v0.w;
        float s1 = qp4.x*v1.x + qp4.y*v1.y + qp4.z*v1.z + qp4.w*v1.w;
        float s2 = qp4.x*v2.x + qp4.y*v2.y + qp4.z*v2.z + qp4.w*v2.w;
        float s3 = qp4.x*v3.x + qp4.y*v3.y + qp4.z*v3.z + qp4.w*v3.w;

        #pragma unroll
        for (int o = 1; o < 16; o <<= 1) {
            s0 += __shfl_xor_sync(0xffffffffu, s0, o);
            s1 += __shfl_xor_sync(0xffffffffu, s1, o);
            s2 += __shfl_xor_sync(0xffffffffu, s2, o);
            s3 += __shfl_xor_sync(0xffffffffu, s3, o);
        }

        float m4 = fmaxf(fmaxf(s0, s1), fmaxf(s2, s3));
        float mn = fmaxf(mx, m4);
        float corr = __expf(mx - mn);     // exp(-inf)=0 on first iteration
        float e0 = __expf(s0 - mn);
        float e1 = __expf(s1 - mn);
        float e2 = __expf(s2 - mn);
        float e3 = __expf(s3 - mn);

        den   = den * corr + ((e0 + e1) + (e2 + e3));
        acc.x = acc.x * corr + (e0*v0.x + e1*v1.x + e2*v2.x + e3*v3.x);
        acc.y = acc.y * corr + (e0*v0.y + e1*v1.y + e2*v2.y + e3*v3.y);
        acc.z = acc.z * corr + (e0*v0.z + e1*v1.z + e2*v2.z + e3*v3.z);
        acc.w = acc.w * corr + (e0*v0.w + e1*v1.w + e2*v2.w + e3*v3.w);
        mx = mn;
    }

    // ---- merge 16 streams -> one partial per CTA, write to scratch ----
    const int sid = w * 2 + half;
    if (laneq == 0) { wmx[sid] = mx; wden[sid] = den; }
    *(float4*)(&wacc[sid][4 * laneq]) = acc;
    __syncthreads();

    if (tid < Dc) {
        float gmx = wmx[0];
        #pragma unroll
        for (int i = 1; i < NSTREAM; ++i) gmx = fmaxf(gmx, wmx[i]);
        float gden = 0.f, r = 0.f;
        #pragma unroll
        for (int i = 0; i < NSTREAM; ++i) {
            float sc = __expf(wmx[i] - gmx);
            gden += sc * wden[i];
            r    += sc * wacc[i][tid];
        }
        g_acc[(size_t)bid * Dc + tid] = r;
        if (tid == 0) { g_mx[bid] = gmx; g_den[bid] = gden; }
    }
}

// =============== k2: merge chunks + gate MLP + Wo + Wc epilogue =============
__global__ __launch_bounds__(128)
void merge_kernel(const float* __restrict__ query,
                  const float* __restrict__ Wo,  const float* __restrict__ bo,
                  const float* __restrict__ Wg1, const float* __restrict__ bg1,
                  const float* __restrict__ Wg2, const float* __restrict__ bg2,
                  const float* __restrict__ null_vec,
                  const float* __restrict__ Wc,  const float* __restrict__ bc,
                  float* __restrict__ out_logits,
                  float* __restrict__ out_gate)
{
    __shared__ float qsh[Hc];
    __shared__ float cmx[CHUNKS], cden[CHUNKS];
    __shared__ float ret[Dc];
    __shared__ float osh[Hc];
    __shared__ float max_sim_sh;
    __shared__ float gate_sh;

    const int b    = blockIdx.x;
    const int tid  = threadIdx.x;
    const int lane = tid & 31;

    if (tid < Hc) qsh[tid] = query[(size_t)b * Hc + tid];
    if (tid < CHUNKS) {
        cmx[tid]  = g_mx [b * CHUNKS + tid];
        cden[tid] = g_den[b * CHUNKS + tid];
    }
    __syncthreads();

    if (tid < Dc) {
        float gmx = cmx[0];
        #pragma unroll
        for (int c = 1; c < CHUNKS; ++c) gmx = fmaxf(gmx, cmx[c]);
        float gden = 0.f, r = 0.f;
        #pragma unroll
        for (int c = 0; c < CHUNKS; ++c) {
            float sc = __expf(cmx[c] - gmx);
            gden += sc * cden[c];
            r    += sc * g_acc[(size_t)(b * CHUNKS + c) * Dc + tid];
        }
        ret[tid] = r / gden;
        if (tid == 0) max_sim_sh = gmx;
    }
    __syncthreads();

    // gate MLP (warp 0)
    if (tid < 32) {
        float hval = bg1[lane];
        #pragma unroll
        for (int h = 0; h < Hc; ++h) hval += qsh[h] * Wg1[h * Gc + lane];
        hval += max_sim_sh * Wg1[Hc * Gc + lane];
        hval = fmaxf(hval, 0.f);
        float z = hval * Wg2[lane];
        #pragma unroll
        for (int o = 16; o > 0; o >>= 1) z += __shfl_xor_sync(0xffffffffu, z, o);
        if (lane == 0) {
            z += bg2[0];
            gate_sh = 1.f / (1.f + __expf(-z));
        }
    }
    __syncthreads();

    const float gate = gate_sh;

    if (tid < Hc) {
        float rh = bo[tid];
        #pragma unroll
        for (int d = 0; d < Dc; ++d) rh += ret[d] * Wo[d * Hc + tid];
        osh[tid] = gate * rh + (1.f - gate) * null_vec[tid];
    }
    __syncthreads();

    if (tid < Vc) {
        float lg = bc[tid];
        #pragma unroll
        for (int h = 0; h < Hc; ++h) lg += osh[h] * Wc[h * Vc + tid];
        out_logits[(size_t)b * Vc + tid] = lg;
    }
    if (tid == 0) out_gate[b] = gate;
}

extern "C" void kernel_launch(void* const* d_in, const int* in_sizes, int n_in,
                              void* d_out, int out_size)
{
    const float* query    = (const float*)d_in[0];
    const float* memory   = (const float*)d_in[1];
    const float* Wq       = (const float*)d_in[2];
    const float* bq       = (const float*)d_in[3];
    const float* Wo       = (const float*)d_in[4];
    const float* bo       = (const float*)d_in[5];
    const float* Wg1      = (const float*)d_in[6];
    const float* bg1      = (const float*)d_in[7];
    const float* Wg2      = (const float*)d_in[8];
    const float* bg2      = (const float*)d_in[9];
    const float* null_vec = (const float*)d_in[10];
    const float* Wc       = (const float*)d_in[11];
    const float* bc       = (const float*)d_in[12];

    const int B = in_sizes[0] / Hc;
    const int M = in_sizes[1] / (B * Dc);

    float* out_logits = (float*)d_out;
    float* out_gate   = (float*)d_out + (size_t)B * Vc;

    qproj_kernel<<<B, 64>>>(query, Wq, bq);
    chunk_kernel<<<B * CHUNKS, 256>>>(memory, M);
    merge_kernel<<<B, 128>>>(query, Wo, bo, Wg1, bg1, Wg2, bg2,
                             null_vec, Wc, bc, out_logits, out_gate);
}